// round 16
// baseline (speedup 1.0000x reference)
#include <cuda_runtime.h>
#include <cuda_fp16.h>
#include <cstdint>

// Problem constants
#define BATCH    2
#define SEQ      8192
#define DM       768
#define NH       12
#define HD       64
#define CHUNKLEN 512
#define NLM      32
#define NCH      16           // SEQ / CHUNKLEN
#define LK       544          // NLM + CHUNKLEN
#define QROWS    (BATCH*SEQ)      // 16384

// Scratch (device globals)
__device__ __align__(16) __half g_xh  [(size_t)QROWS*DM];
__device__ __align__(16) __half g_qh  [(size_t)QROWS*DM];
__device__ __align__(16) __half g_kh  [(size_t)QROWS*DM];   // K proj of x tokens
__device__ __align__(16) __half g_vh  [(size_t)QROWS*DM];   // V proj of x tokens
__device__ __align__(16) __half g_ctxh[(size_t)QROWS*DM];
__device__ __align__(16) __half g_w4[4][DM*DM];             // Wq, Wk, Wv, Wo
__device__ __align__(16) __half g_lmh[128*DM];              // landmark x (64 rows used)
__device__ __align__(16) __half g_lmk[128*DM];              // landmark K proj
__device__ __align__(16) __half g_lmv[128*DM];              // landmark V proj

// ---------------------------------------------------------------------------
// Helpers
// ---------------------------------------------------------------------------
__device__ __forceinline__ uint32_t f2h2(float lo, float hi) {
    __half2 h = __floats2half2_rn(lo, hi);
    return *(uint32_t*)&h;
}

__device__ __forceinline__ void mma_f16(float c[4], const uint32_t a[4], const uint32_t b[2]) {
    asm volatile(
        "mma.sync.aligned.m16n8k16.row.col.f32.f16.f16.f32 "
        "{%0,%1,%2,%3}, {%4,%5,%6,%7}, {%8,%9}, {%0,%1,%2,%3};\n"
        : "+f"(c[0]), "+f"(c[1]), "+f"(c[2]), "+f"(c[3])
        : "r"(a[0]), "r"(a[1]), "r"(a[2]), "r"(a[3]), "r"(b[0]), "r"(b[1]));
}

#define LDSM_X4(r0, r1, r2, r3, addr) \
    asm volatile("ldmatrix.sync.aligned.m8n8.x4.shared.b16 {%0,%1,%2,%3}, [%4];" \
        : "=r"(r0), "=r"(r1), "=r"(r2), "=r"(r3) : "r"(addr))

__device__ __forceinline__ uint32_t cvta_shared(const void* p) {
    uint32_t a;
    asm("{ .reg .u64 t; cvta.to.shared.u64 t, %1; cvt.u32.u64 %0, t; }" : "=r"(a) : "l"(p));
    return a;
}

__device__ __forceinline__ void cp16(uint32_t dst, const void* src) {
    asm volatile("cp.async.cg.shared.global [%0], [%1], 16;" :: "r"(dst), "l"(src) : "memory");
}
#define CP_COMMIT() asm volatile("cp.async.commit_group;" ::: "memory")
#define CP_WAIT0()  asm volatile("cp.async.wait_group 0;" ::: "memory")
#define CP_WAIT1()  asm volatile("cp.async.wait_group 1;" ::: "memory")

// ---------------------------------------------------------------------------
// 0a. fp32 -> fp16 conversion of x
// ---------------------------------------------------------------------------
__global__ void cvt_f2h(const float* __restrict__ s, __half* __restrict__ d) {
    int i = blockIdx.x*blockDim.x + threadIdx.x;
    float4 v = ((const float4*)s)[i];
    uint2 u = { f2h2(v.x, v.y), f2h2(v.z, v.w) };
    ((uint2*)d)[i] = u;
}

// 0b. all four weight matrices in one launch (blockIdx.y selects source)
__global__ void cvt_w4(const float* __restrict__ wq, const float* __restrict__ wk,
                       const float* __restrict__ wv, const float* __restrict__ wo) {
    const float* s = (blockIdx.y == 0) ? wq : (blockIdx.y == 1) ? wk
                   : (blockIdx.y == 2) ? wv : wo;
    int i = blockIdx.x*blockDim.x + threadIdx.x;
    float4 v = ((const float4*)s)[i];
    uint2 u = { f2h2(v.x, v.y), f2h2(v.z, v.w) };
    ((uint2*)g_w4[blockIdx.y])[i] = u;
}

// ---------------------------------------------------------------------------
// 1. Landmarks: mean-pool 32 segments of 256 tokens; write half directly.
// ---------------------------------------------------------------------------
__global__ void landmark_kernel(const float* __restrict__ x) {
    int b = blockIdx.x >> 5, l = blockIdx.x & 31, d = threadIdx.x;
    const float* p = x + ((size_t)(b*SEQ + l*256))*DM + d;
    float s = 0.f;
    #pragma unroll 8
    for (int t = 0; t < 256; t++) s += p[(size_t)t*DM];
    g_lmh[(b*NLM + l)*DM + d] = __float2half_rn(s * (1.f/256.f));
}

// ---------------------------------------------------------------------------
// 2. fp16 GEMM (NT), 64x128 CTA tile, 128 threads (4 warps, warp = 64x32),
//    BK=64, cp.async 2-stage, ldmatrix.x4 frags with REGISTER DOUBLE
//    BUFFERING: k-step ks+1's fragments load while ks's mma chain runs.
//    __launch_bounds__(128,3) -> 170-reg cap gives ptxas room (est ~147).
// ---------------------------------------------------------------------------
struct GArgs {
    const __half* A; const __half* W; const float* bias;
    __half* Ch; float* Cf; int M;
};

#define GA_U32   2304            // A tile: 64 rows * 36 u32
#define GW_U32   4608            // W tile: 128 rows * 36 u32
#define GBUF_U32 6912            // per stage
#define GEMM_SMEM (2*GBUF_U32*4) // 55296 bytes

__global__ __launch_bounds__(128, 3) void gemm_h(GArgs a0, GArgs a1, GArgs a2) {
    const GArgs ga = (blockIdx.z == 0) ? a0 : (blockIdx.z == 1 ? a1 : a2);
    const int m0 = blockIdx.y * 64;
    if (m0 >= ga.M) return;
    const int n0 = blockIdx.x * 128;

    extern __shared__ __align__(16) uint32_t dsm[];
    const uint32_t sb = cvta_shared(dsm);

    const int tid  = threadIdx.x;
    const int lane = tid & 31, warp = tid >> 5;   // 4 warps: wn = warp
    const int gid  = lane >> 2, tig = lane & 3;
    const int sr   = tid >> 3, sg = tid & 7;      // staging: sr 0..15, sg 0..7

    // ldmatrix per-lane address components (rows within a tile)
    const int arow  = (lane & 7) + ((lane >> 3) & 1)*8;          // A: m row
    const int acol4 = (lane >> 4) << 2;                          // A: k-half
    const int brow  = warp*32 + (lane & 7) + ((lane >> 4) << 3); // W: n row
    const int bcol4 = ((lane >> 3) & 1) << 2;                    // W: k-half

    float c[4][4][4];
    #pragma unroll
    for (int mi = 0; mi < 4; mi++)
        #pragma unroll
        for (int ni = 0; ni < 4; ni++)
            #pragma unroll
            for (int r = 0; r < 4; r++) c[mi][ni][r] = 0.f;

    const __half* Asrc = ga.A + (size_t)(m0 + sr)*DM + sg*8;
    const __half* Wsrc = ga.W + (size_t)(n0 + sr)*DM + sg*8;
    const uint32_t dbase = sb + (uint32_t)(sr*144 + sg*16);

    auto stage = [&](int kt, int b) {
        const uint32_t da = dbase + (uint32_t)b * (GBUF_U32*4);
        const uint32_t dw = da + GA_U32*4;
        const __half* as = Asrc + kt*64;
        const __half* ws = Wsrc + kt*64;
        #pragma unroll
        for (int i = 0; i < 4; i++)                    // A: rows sr+16i (0..63)
            cp16(da + i*16*144, as + (size_t)i*16*DM);
        #pragma unroll
        for (int i = 0; i < 8; i++)                    // W: rows sr+16i (0..127)
            cp16(dw + i*16*144, ws + (size_t)i*16*DM);
    };

    stage(0, 0);
    CP_COMMIT();

    for (int kt = 0; kt < DM/64; kt++) {       // 12 chunks
        CP_WAIT0();
        __syncthreads();
        if (kt + 1 < DM/64) { stage(kt + 1, (kt + 1) & 1); CP_COMMIT(); }

        const uint32_t Ab_sb = sb + (uint32_t)(kt & 1)*(GBUF_U32*4);
        const uint32_t Wb_sb = Ab_sb + GA_U32*4;
        const uint32_t a_l = Ab_sb + (uint32_t)(arow*36 + acol4)*4;
        const uint32_t b_l = Wb_sb + (uint32_t)(brow*36 + bcol4)*4;

        // fragment register double-buffer
        uint32_t a[2][4][4], b[2][4][2];

        auto ldfrag = [&](int ks, int buf) {
            #pragma unroll
            for (int mi = 0; mi < 4; mi++)
                LDSM_X4(a[buf][mi][0], a[buf][mi][1], a[buf][mi][2], a[buf][mi][3],
                        a_l + (uint32_t)(mi*16*36 + ks*8)*4);
            #pragma unroll
            for (int p = 0; p < 2; p++)
                LDSM_X4(b[buf][2*p][0], b[buf][2*p][1], b[buf][2*p+1][0], b[buf][2*p+1][1],
                        b_l + (uint32_t)(p*16*36 + ks*8)*4);
        };

        ldfrag(0, 0);
        #pragma unroll
        for (int ks = 0; ks < 4; ks++) {
            const int cur = ks & 1;
            if (ks < 3) ldfrag(ks + 1, cur ^ 1);   // overlap with mma below
            #pragma unroll
            for (int mi = 0; mi < 4; mi++)
                #pragma unroll
                for (int ni = 0; ni < 4; ni++)
                    mma_f16(c[mi][ni], a[cur][mi], b[cur][ni]);
        }
    }

    // epilogue: bias (fp32) + store half or float
    #pragma unroll
    for (int mi = 0; mi < 4; mi++) {
        int r0 = m0 + mi*16 + gid;
        #pragma unroll
        for (int ni = 0; ni < 4; ni++) {
            int col = n0 + warp*32 + ni*8 + (tig << 1);
            float2 bv = *(const float2*)(ga.bias + col);
            float v00 = c[mi][ni][0] + bv.x, v01 = c[mi][ni][1] + bv.y;
            float v10 = c[mi][ni][2] + bv.x, v11 = c[mi][ni][3] + bv.y;
            if (ga.Cf) {
                *(float2*)(ga.Cf + (size_t)r0*DM + col)     = make_float2(v00, v01);
                *(float2*)(ga.Cf + (size_t)(r0+8)*DM + col) = make_float2(v10, v11);
            } else {
                *(uint32_t*)(ga.Ch + (size_t)r0*DM + col)     = f2h2(v00, v01);
                *(uint32_t*)(ga.Ch + (size_t)(r0+8)*DM + col) = f2h2(v10, v11);
            }
        }
    }
}

// ---------------------------------------------------------------------------
// 3. fp16 flash attention with 64-wide softmax passes (round-14 version).
//    Pass 0: 32 landmark rows. Passes 1..8: 64 token rows each.
//    Dynamic smem: Ks[2][64][36] | Vs[2][64][36] | Ps[128][36] = 55296 B.
// ---------------------------------------------------------------------------
#define AT_KS_OFF 0
#define AT_VS_OFF 18432
#define AT_PS_OFF 36864
#define ATTN_SMEM 55296

__global__ __launch_bounds__(256, 2) void attn_kernel() {
    extern __shared__ __align__(16) uint32_t asm_dsm[];
    uint32_t* Ps = asm_dsm + AT_PS_OFF/4;      // [128][36] u32

    const int qt = blockIdx.x, h = blockIdx.y, bc = blockIdx.z;
    const int tid  = threadIdx.x;
    const int lane = tid & 31, warp = tid >> 5;
    const int gid  = lane >> 2, tig = lane & 3;
    const int bb = bc >> 4, ch = bc & 15;

    const int qrow0 = bc*CHUNKLEN + qt*128 + warp*16 + gid;
    const int sr = tid >> 3, sg = tid & 7;
    const int pr0 = warp*16 + gid;

    const uint32_t ks_sb = cvta_shared(asm_dsm) + AT_KS_OFF;
    const uint32_t vs_sb = cvta_shared(asm_dsm) + AT_VS_OFF;
    const uint32_t kv_doff = (uint32_t)(sr*144 + sg*16);

    const int krow  = (lane & 7) + ((lane >> 4) << 3);
    const int kcol4 = ((lane >> 3) & 1) << 2;

    const size_t coloff = (size_t)h*HD + sg*8;
    const __half* kx  = g_kh  + ((size_t)(bb*SEQ + ch*CHUNKLEN + sr))*DM + coloff;
    const __half* vx  = g_vh  + ((size_t)(bb*SEQ + ch*CHUNKLEN + sr))*DM + coloff;
    const __half* klm = g_lmk + ((size_t)(bb*NLM + sr))*DM + coloff;
    const __half* vlm = g_lmv + ((size_t)(bb*NLM + sr))*DM + coloff;

    auto stage_tok = [&](int i, int b) {
        const size_t off = (size_t)i*64*DM;
        const uint32_t dk = ks_sb + (uint32_t)b*(64*144) + kv_doff;
        const uint32_t dv = vs_sb + (uint32_t)b*(64*144) + kv_doff;
        cp16(dk,          kx + off);
        cp16(dv,          vx + off);
        cp16(dk + 32*144, kx + off + (size_t)32*DM);
        cp16(dv + 32*144, vx + off + (size_t)32*DM);
    };

    uint32_t qa[4][4];
    {
        const __half* qp = g_qh + (size_t)qrow0*DM + h*HD;
        #pragma unroll
        for (int ks = 0; ks < 4; ks++) {
            int cc = ks*16 + 2*tig;
            qa[ks][0] = *(const uint32_t*)(qp + cc);
            qa[ks][1] = *(const uint32_t*)(qp + (size_t)8*DM + cc);
            qa[ks][2] = *(const uint32_t*)(qp + cc + 8);
            qa[ks][3] = *(const uint32_t*)(qp + (size_t)8*DM + cc + 8);
        }
    }

    float o[8][4];
    #pragma unroll
    for (int ni = 0; ni < 8; ni++)
        #pragma unroll
        for (int j = 0; j < 4; j++) o[ni][j] = 0.f;
    float m0r = -1e30f, m1r = -1e30f;
    float l0 = 0.f, l1 = 0.f;

    cp16(ks_sb + kv_doff, klm);
    cp16(vs_sb + kv_doff, vlm);
    CP_COMMIT();
    stage_tok(0, 1);
    CP_COMMIT();

    // ======== pass 0: 32 landmark rows (buf0) ========
    CP_WAIT1();
    __syncthreads();
    {
        float s[4][4];
        #pragma unroll
        for (int ni = 0; ni < 4; ni++)
            #pragma unroll
            for (int j = 0; j < 4; j++) s[ni][j] = 0.f;
        const uint32_t k_l = ks_sb + (uint32_t)(krow*36 + kcol4)*4;
        #pragma unroll
        for (int ks = 0; ks < 4; ks++) {
            uint32_t bf[4][2];
            #pragma unroll
            for (int p = 0; p < 2; p++)
                LDSM_X4(bf[2*p][0], bf[2*p][1], bf[2*p+1][0], bf[2*p+1][1],
                        k_l + (uint32_t)(p*16*36 + ks*8)*4);
            #pragma unroll
            for (int ni = 0; ni < 4; ni++)
                mma_f16(s[ni], qa[ks], bf[ni]);
        }
        #pragma unroll
        for (int ni = 0; ni < 4; ni++)
            #pragma unroll
            for (int j = 0; j < 4; j++) s[ni][j] *= 0.125f;

        float tm0 = s[0][0], tm1 = s[0][2];
        #pragma unroll
        for (int ni = 0; ni < 4; ni++) {
            tm0 = fmaxf(tm0, fmaxf(s[ni][0], s[ni][1]));
            tm1 = fmaxf(tm1, fmaxf(s[ni][2], s[ni][3]));
        }
        tm0 = fmaxf(tm0, __shfl_xor_sync(0xffffffffu, tm0, 1));
        tm0 = fmaxf(tm0, __shfl_xor_sync(0xffffffffu, tm0, 2));
        tm1 = fmaxf(tm1, __shfl_xor_sync(0xffffffffu, tm1, 1));
        tm1 = fmaxf(tm1, __shfl_xor_sync(0xffffffffu, tm1, 2));
        m0r = tm0; m1r = tm1;

        #pragma unroll
        for (int ni = 0; ni < 4; ni++) {
            float p00 = __expf(s[ni][0] - tm0);
            float p01 = __expf(s[ni][1] - tm0);
            float p10 = __expf(s[ni][2] - tm1);
            float p11 = __expf(s[ni][3] - tm1);
            l0 += p00 + p01;
            l1 += p10 + p11;
            Ps[(pr0    )*36 + ni*4 + tig] = f2h2(p00, p01);
            Ps[(pr0 + 8)*36 + ni*4 + tig] = f2h2(p10, p11);
        }
        __syncwarp();

        const uint32_t vs_lanerow = vs_sb + (uint32_t)(lane & 15)*144;
        #pragma unroll
        for (int ka = 0; ka < 2; ka++) {
            uint32_t a[4];
            a[0] = Ps[(pr0    )*36 + ka*8 + tig];
            a[1] = Ps[(pr0 + 8)*36 + ka*8 + tig];
            a[2] = Ps[(pr0    )*36 + ka*8 + tig + 4];
            a[3] = Ps[(pr0 + 8)*36 + ka*8 + tig + 4];
            const uint32_t rowaddr = vs_lanerow + (uint32_t)(16*ka)*144;
            #pragma unroll
            for (int ni = 0; ni < 8; ni++) {
                uint32_t bf[2];
                asm volatile(
                    "ldmatrix.sync.aligned.m8n8.x2.trans.shared.b16 {%0,%1}, [%2];"
                    : "=r"(bf[0]), "=r"(bf[1]) : "r"(rowaddr + (uint32_t)(ni*16)));
                mma_f16(o[ni], a, bf);
            }
        }
    }

    // ======== passes 1..8: 64 token rows each ========
    for (int i = 0; i < 8; i++) {
        const int b = (i & 1) ^ 1;
        CP_WAIT0();
        __syncthreads();
        if (i < 7) { stage_tok(i + 1, b ^ 1); CP_COMMIT(); }

        float s[8][4];
        #pragma unroll
        for (int ni = 0; ni < 8; ni++)
            #pragma unroll
            for (int j = 0; j < 4; j++) s[ni][j] = 0.f;
        const uint32_t k_l = ks_sb + (uint32_t)b*(64*144) + (uint32_t)(krow*36 + kcol4)*4;
        #pragma unroll
        for (int ks = 0; ks < 4; ks++) {
            uint32_t bf[8][2];
            #pragma unroll
            for (int p = 0; p < 4; p++)
                LDSM_X4(bf[2*p][0], bf[2*p][1], bf[2*p+1][0], bf[2*p+1][1],
                        k_l + (uint32_t)(p*16*36 + ks*8)*4);
            #pragma unroll
            for (int ni = 0; ni < 8; ni++)
                mma_f16(s[ni], qa[ks], bf[ni]);
        }
        #pragma unroll
        for (int ni = 0; ni < 8; ni++)
            #pragma unroll
            for (int j = 0; j < 4; j++) s[ni][j] *= 0.125f;

        float tm0 = s[0][0], tm1 = s[0][2];
        #pragma unroll
        for (int ni = 0; ni < 8; ni++) {
            tm0 = fmaxf(tm0, fmaxf(s[ni][0], s[ni][1]));
            tm1 = fmaxf(tm1, fmaxf(s[ni][2], s[ni][3]));
        }
        tm0 = fmaxf(tm0, __shfl_xor_sync(0xffffffffu, tm0, 1));
        tm0 = fmaxf(tm0, __shfl_xor_sync(0xffffffffu, tm0, 2));
        tm1 = fmaxf(tm1, __shfl_xor_sync(0xffffffffu, tm1, 1));
        tm1 = fmaxf(tm1, __shfl_xor_sync(0xffffffffu, tm1, 2));
        float mn0 = fmaxf(m0r, tm0), mn1 = fmaxf(m1r, tm1);
        float cr0 = __expf(m0r - mn0), cr1 = __expf(m1r - mn1);
        m0r = mn0; m1r = mn1;
        l0 *= cr0; l1 *= cr1;
        #pragma unroll
        for (int ni = 0; ni < 8; ni++) {
            o[ni][0] *= cr0; o[ni][1] *= cr0;
            o[ni][2] *= cr1; o[ni][3] *= cr1;
        }

        #pragma unroll
        for (int ni = 0; ni < 8; ni++) {
            float p00 = __expf(s[ni][0] - mn0);
            float p01 = __expf(s[ni][1] - mn0);
            float p10 = __expf(s[ni][2] - mn1);
            float p11 = __expf(s[ni][3] - mn1);
            l0 += p00 + p01;
            l1 += p10 + p11;
            Ps[(pr0    )*36 + ni*4 + tig] = f2h2(p00, p01);
            Ps[(pr0 + 8)*36 + ni*4 + tig] = f2h2(p10, p11);
        }
        __syncwarp();

        const uint32_t vs_lanerow = vs_sb + (uint32_t)b*(64*144) + (uint32_t)(lane & 15)*144;
        #pragma unroll
        for (int ka = 0; ka < 4; ka++) {
            uint32_t a[4];
            a[0] = Ps[(pr0    )*36 + ka*8 + tig];
            a[1] = Ps[(pr0 + 8)*36 + ka*8 + tig];
            a[2] = Ps[(pr0    )*36 + ka*8 + tig + 4];
            a[3] = Ps[(pr0 + 8)*36 + ka*8 + tig + 4];
            const uint32_t rowaddr = vs_lanerow + (uint32_t)(16*ka)*144;
            #pragma unroll
            for (int ni = 0; ni < 8; ni++) {
                uint32_t bf[2];
                asm volatile(
                    "ldmatrix.sync.aligned.m8n8.x2.trans.shared.b16 {%0,%1}, [%2];"
                    : "=r"(bf[0]), "=r"(bf[1]) : "r"(rowaddr + (uint32_t)(ni*16)));
                mma_f16(o[ni], a, bf);
            }
        }
    }

    // ---- finalize: write ctx as half ----
    l0 += __shfl_xor_sync(0xffffffffu, l0, 1);
    l0 += __shfl_xor_sync(0xffffffffu, l0, 2);
    l1 += __shfl_xor_sync(0xffffffffu, l1, 1);
    l1 += __shfl_xor_sync(0xffffffffu, l1, 2);
    float inv0 = 1.f / l0, inv1 = 1.f / l1;

    __half* op = g_ctxh + (size_t)qrow0*DM + h*HD;
    #pragma unroll
    for (int ni = 0; ni < 8; ni++) {
        int col = ni*8 + (tig << 1);
        *(uint32_t*)(op + col)                = f2h2(o[ni][0]*inv0, o[ni][1]*inv0);
        *(uint32_t*)(op + (size_t)8*DM + col) = f2h2(o[ni][2]*inv1, o[ni][3]*inv1);
    }
}

// ---------------------------------------------------------------------------
// Launch
// ---------------------------------------------------------------------------
extern "C" void kernel_launch(void* const* d_in, const int* in_sizes, int n_in,
                              void* d_out, int out_size)
{
    const float* x  = (const float*)d_in[0];
    const float* Wq = (const float*)d_in[1];
    const float* bq = (const float*)d_in[2];
    const float* Wk = (const float*)d_in[3];
    const float* bk = (const float*)d_in[4];
    const float* Wv = (const float*)d_in[5];
    const float* bv = (const float*)d_in[6];
    const float* Wo = (const float*)d_in[7];
    const float* bo = (const float*)d_in[8];
    float* out = (float*)d_out;

    __half *p_xh, *p_qh, *p_kh, *p_vh, *p_ctxh, *p_w4, *p_lmh, *p_lmk, *p_lmv;
    cudaGetSymbolAddress((void**)&p_xh,   g_xh);
    cudaGetSymbolAddress((void**)&p_qh,   g_qh);
    cudaGetSymbolAddress((void**)&p_kh,   g_kh);
    cudaGetSymbolAddress((void**)&p_vh,   g_vh);
    cudaGetSymbolAddress((void**)&p_ctxh, g_ctxh);
    cudaGetSymbolAddress((void**)&p_w4,   g_w4);
    cudaGetSymbolAddress((void**)&p_lmh,  g_lmh);
    cudaGetSymbolAddress((void**)&p_lmk,  g_lmk);
    cudaGetSymbolAddress((void**)&p_lmv,  g_lmv);

    cudaFuncSetAttribute(gemm_h, cudaFuncAttributeMaxDynamicSharedMemorySize, GEMM_SMEM);
    cudaFuncSetAttribute(attn_kernel, cudaFuncAttributeMaxDynamicSharedMemorySize, ATTN_SMEM);

    cvt_f2h<<<(QROWS*DM/4)/256, 256>>>(x, p_xh);
    cvt_w4<<<dim3((DM*DM/4)/256, 4), 256>>>(Wq, Wk, Wv, Wo);
    landmark_kernel<<<BATCH*NLM, DM>>>(x);

    // Q, K, V projections of x tokens, fused (shared A tiles via L2)
    GArgs aq = { p_xh, p_w4 + 0*(size_t)DM*DM, bq, p_qh, nullptr, QROWS };
    GArgs ak = { p_xh, p_w4 + 1*(size_t)DM*DM, bk, p_kh, nullptr, QROWS };
    GArgs av = { p_xh, p_w4 + 2*(size_t)DM*DM, bv, p_vh, nullptr, QROWS };
    gemm_h<<<dim3(6, QROWS/64, 3), 128, GEMM_SMEM>>>(aq, ak, av);

    // landmark K/V projections (64 live rows -> 1 m-tile of 64)
    GArgs lk = { p_lmh, p_w4 + 1*(size_t)DM*DM, bk, p_lmk, nullptr, 128 };
    GArgs lv = { p_lmh, p_w4 + 2*(size_t)DM*DM, bv, p_lmv, nullptr, 128 };
    gemm_h<<<dim3(6, 2, 2), 128, GEMM_SMEM>>>(lk, lv, lv);

    attn_kernel<<<dim3(4, NH, BATCH*NCH), 256, ATTN_SMEM>>>();

    GArgs ao = { p_ctxh, p_w4 + 3*(size_t)DM*DM, bo, nullptr, out, QROWS };
    gemm_h<<<dim3(6, QROWS/64, 1), 128, GEMM_SMEM>>>(ao, ao, ao);
}

// round 17
// speedup vs baseline: 1.0657x; 1.0657x over previous
#include <cuda_runtime.h>
#include <cuda_fp16.h>
#include <cstdint>

// Problem constants
#define BATCH    2
#define SEQ      8192
#define DM       768
#define NH       12
#define HD       64
#define CHUNKLEN 512
#define NLM      32
#define NCH      16           // SEQ / CHUNKLEN
#define LK       544          // NLM + CHUNKLEN
#define QROWS    (BATCH*SEQ)      // 16384

// Scratch (device globals)
__device__ __align__(16) __half g_xh  [(size_t)QROWS*DM];
__device__ __align__(16) __half g_qh  [(size_t)QROWS*DM];
__device__ __align__(16) __half g_kh  [(size_t)QROWS*DM];   // K proj of x tokens
__device__ __align__(16) __half g_vh  [(size_t)QROWS*DM];   // V proj of x tokens
__device__ __align__(16) __half g_ctxh[(size_t)QROWS*DM];
__device__ __align__(16) __half g_w4[4][DM*DM];             // Wq, Wk, Wv, Wo
__device__ __align__(16) __half g_lmh[128*DM];              // landmark x (64 rows used)
__device__ __align__(16) __half g_lmk[128*DM];              // landmark K proj
__device__ __align__(16) __half g_lmv[128*DM];              // landmark V proj

// ---------------------------------------------------------------------------
// Helpers
// ---------------------------------------------------------------------------
__device__ __forceinline__ uint32_t f2h2(float lo, float hi) {
    __half2 h = __floats2half2_rn(lo, hi);
    return *(uint32_t*)&h;
}

__device__ __forceinline__ void mma_f16(float c[4], const uint32_t a[4], const uint32_t b[2]) {
    asm volatile(
        "mma.sync.aligned.m16n8k16.row.col.f32.f16.f16.f32 "
        "{%0,%1,%2,%3}, {%4,%5,%6,%7}, {%8,%9}, {%0,%1,%2,%3};\n"
        : "+f"(c[0]), "+f"(c[1]), "+f"(c[2]), "+f"(c[3])
        : "r"(a[0]), "r"(a[1]), "r"(a[2]), "r"(a[3]), "r"(b[0]), "r"(b[1]));
}

#define LDSM_X4(r0, r1, r2, r3, addr) \
    asm volatile("ldmatrix.sync.aligned.m8n8.x4.shared.b16 {%0,%1,%2,%3}, [%4];" \
        : "=r"(r0), "=r"(r1), "=r"(r2), "=r"(r3) : "r"(addr))

__device__ __forceinline__ uint32_t cvta_shared(const void* p) {
    uint32_t a;
    asm("{ .reg .u64 t; cvta.to.shared.u64 t, %1; cvt.u32.u64 %0, t; }" : "=r"(a) : "l"(p));
    return a;
}

__device__ __forceinline__ void cp16(uint32_t dst, const void* src) {
    asm volatile("cp.async.cg.shared.global [%0], [%1], 16;" :: "r"(dst), "l"(src) : "memory");
}
#define CP_COMMIT() asm volatile("cp.async.commit_group;" ::: "memory")
#define CP_WAIT0()  asm volatile("cp.async.wait_group 0;" ::: "memory")
#define CP_WAIT1()  asm volatile("cp.async.wait_group 1;" ::: "memory")

// ---------------------------------------------------------------------------
// 0a. fp32 -> fp16 conversion of x
// ---------------------------------------------------------------------------
__global__ void cvt_f2h(const float* __restrict__ s, __half* __restrict__ d) {
    int i = blockIdx.x*blockDim.x + threadIdx.x;
    float4 v = ((const float4*)s)[i];
    uint2 u = { f2h2(v.x, v.y), f2h2(v.z, v.w) };
    ((uint2*)d)[i] = u;
}

// 0b. all four weight matrices in one launch (blockIdx.y selects source)
__global__ void cvt_w4(const float* __restrict__ wq, const float* __restrict__ wk,
                       const float* __restrict__ wv, const float* __restrict__ wo) {
    const float* s = (blockIdx.y == 0) ? wq : (blockIdx.y == 1) ? wk
                   : (blockIdx.y == 2) ? wv : wo;
    int i = blockIdx.x*blockDim.x + threadIdx.x;
    float4 v = ((const float4*)s)[i];
    uint2 u = { f2h2(v.x, v.y), f2h2(v.z, v.w) };
    ((uint2*)g_w4[blockIdx.y])[i] = u;
}

// ---------------------------------------------------------------------------
// 1. Landmarks: mean-pool 32 segments of 256 tokens; write half directly.
// ---------------------------------------------------------------------------
__global__ void landmark_kernel(const float* __restrict__ x) {
    int b = blockIdx.x >> 5, l = blockIdx.x & 31, d = threadIdx.x;
    const float* p = x + ((size_t)(b*SEQ + l*256))*DM + d;
    float s = 0.f;
    #pragma unroll 8
    for (int t = 0; t < 256; t++) s += p[(size_t)t*DM];
    g_lmh[(b*NLM + l)*DM + d] = __float2half_rn(s * (1.f/256.f));
}

// ---------------------------------------------------------------------------
// 2. fp16 GEMM (NT), 64x128 CTA tile, 128 threads (4 warps, warp = 64x32),
//    BK=64, cp.async 2-stage, ldmatrix.x4 frags. 4 CTAs/SM (round-15 config;
//    the round-16 register double-buffer regressed and is reverted).
// ---------------------------------------------------------------------------
struct GArgs {
    const __half* A; const __half* W; const float* bias;
    __half* Ch; float* Cf; int M;
};

#define GA_U32   2304            // A tile: 64 rows * 36 u32
#define GW_U32   4608            // W tile: 128 rows * 36 u32
#define GBUF_U32 6912            // per stage
#define GEMM_SMEM (2*GBUF_U32*4) // 55296 bytes

__global__ __launch_bounds__(128, 4) void gemm_h(GArgs a0, GArgs a1, GArgs a2) {
    const GArgs ga = (blockIdx.z == 0) ? a0 : (blockIdx.z == 1 ? a1 : a2);
    const int m0 = blockIdx.y * 64;
    if (m0 >= ga.M) return;
    const int n0 = blockIdx.x * 128;

    extern __shared__ __align__(16) uint32_t dsm[];
    const uint32_t sb = cvta_shared(dsm);

    const int tid  = threadIdx.x;
    const int lane = tid & 31, warp = tid >> 5;   // 4 warps: wn = warp
    const int gid  = lane >> 2, tig = lane & 3;
    const int sr   = tid >> 3, sg = tid & 7;      // staging: sr 0..15, sg 0..7

    const int arow  = (lane & 7) + ((lane >> 3) & 1)*8;          // A: m row
    const int acol4 = (lane >> 4) << 2;                          // A: k-half
    const int brow  = warp*32 + (lane & 7) + ((lane >> 4) << 3); // W: n row
    const int bcol4 = ((lane >> 3) & 1) << 2;                    // W: k-half

    float c[4][4][4];
    #pragma unroll
    for (int mi = 0; mi < 4; mi++)
        #pragma unroll
        for (int ni = 0; ni < 4; ni++)
            #pragma unroll
            for (int r = 0; r < 4; r++) c[mi][ni][r] = 0.f;

    const __half* Asrc = ga.A + (size_t)(m0 + sr)*DM + sg*8;
    const __half* Wsrc = ga.W + (size_t)(n0 + sr)*DM + sg*8;
    const uint32_t dbase = sb + (uint32_t)(sr*144 + sg*16);

    auto stage = [&](int kt, int b) {
        const uint32_t da = dbase + (uint32_t)b * (GBUF_U32*4);
        const uint32_t dw = da + GA_U32*4;
        const __half* as = Asrc + kt*64;
        const __half* ws = Wsrc + kt*64;
        #pragma unroll
        for (int i = 0; i < 4; i++)
            cp16(da + i*16*144, as + (size_t)i*16*DM);
        #pragma unroll
        for (int i = 0; i < 8; i++)
            cp16(dw + i*16*144, ws + (size_t)i*16*DM);
    };

    stage(0, 0);
    CP_COMMIT();

    for (int kt = 0; kt < DM/64; kt++) {       // 12 chunks
        CP_WAIT0();
        __syncthreads();
        if (kt + 1 < DM/64) { stage(kt + 1, (kt + 1) & 1); CP_COMMIT(); }

        const uint32_t Ab_sb = sb + (uint32_t)(kt & 1)*(GBUF_U32*4);
        const uint32_t Wb_sb = Ab_sb + GA_U32*4;
        const uint32_t a_l = Ab_sb + (uint32_t)(arow*36 + acol4)*4;
        const uint32_t b_l = Wb_sb + (uint32_t)(brow*36 + bcol4)*4;

        #pragma unroll
        for (int ks = 0; ks < 4; ks++) {
            uint32_t a[4][4], b[4][2];
            #pragma unroll
            for (int mi = 0; mi < 4; mi++)
                LDSM_X4(a[mi][0], a[mi][1], a[mi][2], a[mi][3],
                        a_l + (uint32_t)(mi*16*36 + ks*8)*4);
            #pragma unroll
            for (int p = 0; p < 2; p++)
                LDSM_X4(b[2*p][0], b[2*p][1], b[2*p+1][0], b[2*p+1][1],
                        b_l + (uint32_t)(p*16*36 + ks*8)*4);
            #pragma unroll
            for (int mi = 0; mi < 4; mi++)
                #pragma unroll
                for (int ni = 0; ni < 4; ni++)
                    mma_f16(c[mi][ni], a[mi], b[ni]);
        }
    }

    // epilogue: bias (fp32) + store half or float
    #pragma unroll
    for (int mi = 0; mi < 4; mi++) {
        int r0 = m0 + mi*16 + gid;
        #pragma unroll
        for (int ni = 0; ni < 4; ni++) {
            int col = n0 + warp*32 + ni*8 + (tig << 1);
            float2 bv = *(const float2*)(ga.bias + col);
            float v00 = c[mi][ni][0] + bv.x, v01 = c[mi][ni][1] + bv.y;
            float v10 = c[mi][ni][2] + bv.x, v11 = c[mi][ni][3] + bv.y;
            if (ga.Cf) {
                *(float2*)(ga.Cf + (size_t)r0*DM + col)     = make_float2(v00, v01);
                *(float2*)(ga.Cf + (size_t)(r0+8)*DM + col) = make_float2(v10, v11);
            } else {
                *(uint32_t*)(ga.Ch + (size_t)r0*DM + col)     = f2h2(v00, v01);
                *(uint32_t*)(ga.Ch + (size_t)(r0+8)*DM + col) = f2h2(v10, v11);
            }
        }
    }
}

// ---------------------------------------------------------------------------
// 3. fp16 flash attention, 64-wide softmax passes, NO P smem round-trip:
//    the QK^T C-fragment layout IS the PV A-fragment layout (FA-2 trick),
//    so exp() outputs are packed straight into mma A operands.
//    Dynamic smem: Ks[2][64][36] | Vs[2][64][36] = 36864 B.
// ---------------------------------------------------------------------------
#define AT_KS_OFF 0
#define AT_VS_OFF 18432
#define ATTN_SMEM 36864

__global__ __launch_bounds__(256, 2) void attn_kernel() {
    extern __shared__ __align__(16) uint32_t asm_dsm[];

    const int qt = blockIdx.x, h = blockIdx.y, bc = blockIdx.z;
    const int tid  = threadIdx.x;
    const int lane = tid & 31, warp = tid >> 5;
    const int gid  = lane >> 2, tig = lane & 3;
    const int bb = bc >> 4, ch = bc & 15;

    const int qrow0 = bc*CHUNKLEN + qt*128 + warp*16 + gid;
    const int sr = tid >> 3, sg = tid & 7;

    const uint32_t ks_sb = cvta_shared(asm_dsm) + AT_KS_OFF;
    const uint32_t vs_sb = cvta_shared(asm_dsm) + AT_VS_OFF;
    const uint32_t kv_doff = (uint32_t)(sr*144 + sg*16);

    const int krow  = (lane & 7) + ((lane >> 4) << 3);
    const int kcol4 = ((lane >> 3) & 1) << 2;

    const size_t coloff = (size_t)h*HD + sg*8;
    const __half* kx  = g_kh  + ((size_t)(bb*SEQ + ch*CHUNKLEN + sr))*DM + coloff;
    const __half* vx  = g_vh  + ((size_t)(bb*SEQ + ch*CHUNKLEN + sr))*DM + coloff;
    const __half* klm = g_lmk + ((size_t)(bb*NLM + sr))*DM + coloff;
    const __half* vlm = g_lmv + ((size_t)(bb*NLM + sr))*DM + coloff;

    auto stage_tok = [&](int i, int b) {
        const size_t off = (size_t)i*64*DM;
        const uint32_t dk = ks_sb + (uint32_t)b*(64*144) + kv_doff;
        const uint32_t dv = vs_sb + (uint32_t)b*(64*144) + kv_doff;
        cp16(dk,          kx + off);
        cp16(dv,          vx + off);
        cp16(dk + 32*144, kx + off + (size_t)32*DM);
        cp16(dv + 32*144, vx + off + (size_t)32*DM);
    };

    uint32_t qa[4][4];
    {
        const __half* qp = g_qh + (size_t)qrow0*DM + h*HD;
        #pragma unroll
        for (int ks = 0; ks < 4; ks++) {
            int cc = ks*16 + 2*tig;
            qa[ks][0] = *(const uint32_t*)(qp + cc);
            qa[ks][1] = *(const uint32_t*)(qp + (size_t)8*DM + cc);
            qa[ks][2] = *(const uint32_t*)(qp + cc + 8);
            qa[ks][3] = *(const uint32_t*)(qp + (size_t)8*DM + cc + 8);
        }
    }

    float o[8][4];
    #pragma unroll
    for (int ni = 0; ni < 8; ni++)
        #pragma unroll
        for (int j = 0; j < 4; j++) o[ni][j] = 0.f;
    float m0r = -1e30f, m1r = -1e30f;
    float l0 = 0.f, l1 = 0.f;

    cp16(ks_sb + kv_doff, klm);
    cp16(vs_sb + kv_doff, vlm);
    CP_COMMIT();
    stage_tok(0, 1);
    CP_COMMIT();

    // ======== pass 0: 32 landmark rows (buf0) ========
    CP_WAIT1();
    __syncthreads();
    {
        float s[4][4];
        #pragma unroll
        for (int ni = 0; ni < 4; ni++)
            #pragma unroll
            for (int j = 0; j < 4; j++) s[ni][j] = 0.f;
        const uint32_t k_l = ks_sb + (uint32_t)(krow*36 + kcol4)*4;
        #pragma unroll
        for (int ks = 0; ks < 4; ks++) {
            uint32_t bf[4][2];
            #pragma unroll
            for (int p = 0; p < 2; p++)
                LDSM_X4(bf[2*p][0], bf[2*p][1], bf[2*p+1][0], bf[2*p+1][1],
                        k_l + (uint32_t)(p*16*36 + ks*8)*4);
            #pragma unroll
            for (int ni = 0; ni < 4; ni++)
                mma_f16(s[ni], qa[ks], bf[ni]);
        }
        #pragma unroll
        for (int ni = 0; ni < 4; ni++)
            #pragma unroll
            for (int j = 0; j < 4; j++) s[ni][j] *= 0.125f;

        float tm0 = s[0][0], tm1 = s[0][2];
        #pragma unroll
        for (int ni = 0; ni < 4; ni++) {
            tm0 = fmaxf(tm0, fmaxf(s[ni][0], s[ni][1]));
            tm1 = fmaxf(tm1, fmaxf(s[ni][2], s[ni][3]));
        }
        tm0 = fmaxf(tm0, __shfl_xor_sync(0xffffffffu, tm0, 1));
        tm0 = fmaxf(tm0, __shfl_xor_sync(0xffffffffu, tm0, 2));
        tm1 = fmaxf(tm1, __shfl_xor_sync(0xffffffffu, tm1, 1));
        tm1 = fmaxf(tm1, __shfl_xor_sync(0xffffffffu, tm1, 2));
        m0r = tm0; m1r = tm1;

        // P packed directly into A-frags (C-layout == A-layout)
        uint32_t ph0[4], ph1[4];
        #pragma unroll
        for (int ni = 0; ni < 4; ni++) {
            float p00 = __expf(s[ni][0] - tm0);
            float p01 = __expf(s[ni][1] - tm0);
            float p10 = __expf(s[ni][2] - tm1);
            float p11 = __expf(s[ni][3] - tm1);
            l0 += p00 + p01;
            l1 += p10 + p11;
            ph0[ni] = f2h2(p00, p01);
            ph1[ni] = f2h2(p10, p11);
        }

        const uint32_t vs_lanerow = vs_sb + (uint32_t)(lane & 15)*144;
        #pragma unroll
        for (int ka = 0; ka < 2; ka++) {
            uint32_t a[4] = { ph0[2*ka], ph1[2*ka], ph0[2*ka+1], ph1[2*ka+1] };
            const uint32_t rowaddr = vs_lanerow + (uint32_t)(16*ka)*144;
            #pragma unroll
            for (int ni = 0; ni < 8; ni++) {
                uint32_t bf[2];
                asm volatile(
                    "ldmatrix.sync.aligned.m8n8.x2.trans.shared.b16 {%0,%1}, [%2];"
                    : "=r"(bf[0]), "=r"(bf[1]) : "r"(rowaddr + (uint32_t)(ni*16)));
                mma_f16(o[ni], a, bf);
            }
        }
    }

    // ======== passes 1..8: 64 token rows each ========
    for (int i = 0; i < 8; i++) {
        const int b = (i & 1) ^ 1;
        CP_WAIT0();
        __syncthreads();
        if (i < 7) { stage_tok(i + 1, b ^ 1); CP_COMMIT(); }

        float s[8][4];
        #pragma unroll
        for (int ni = 0; ni < 8; ni++)
            #pragma unroll
            for (int j = 0; j < 4; j++) s[ni][j] = 0.f;
        const uint32_t k_l = ks_sb + (uint32_t)b*(64*144) + (uint32_t)(krow*36 + kcol4)*4;
        #pragma unroll
        for (int ks = 0; ks < 4; ks++) {
            uint32_t bf[8][2];
            #pragma unroll
            for (int p = 0; p < 4; p++)
                LDSM_X4(bf[2*p][0], bf[2*p][1], bf[2*p+1][0], bf[2*p+1][1],
                        k_l + (uint32_t)(p*16*36 + ks*8)*4);
            #pragma unroll
            for (int ni = 0; ni < 8; ni++)
                mma_f16(s[ni], qa[ks], bf[ni]);
        }
        #pragma unroll
        for (int ni = 0; ni < 8; ni++)
            #pragma unroll
            for (int j = 0; j < 4; j++) s[ni][j] *= 0.125f;

        float tm0 = s[0][0], tm1 = s[0][2];
        #pragma unroll
        for (int ni = 0; ni < 8; ni++) {
            tm0 = fmaxf(tm0, fmaxf(s[ni][0], s[ni][1]));
            tm1 = fmaxf(tm1, fmaxf(s[ni][2], s[ni][3]));
        }
        tm0 = fmaxf(tm0, __shfl_xor_sync(0xffffffffu, tm0, 1));
        tm0 = fmaxf(tm0, __shfl_xor_sync(0xffffffffu, tm0, 2));
        tm1 = fmaxf(tm1, __shfl_xor_sync(0xffffffffu, tm1, 1));
        tm1 = fmaxf(tm1, __shfl_xor_sync(0xffffffffu, tm1, 2));
        float mn0 = fmaxf(m0r, tm0), mn1 = fmaxf(m1r, tm1);
        float cr0 = __expf(m0r - mn0), cr1 = __expf(m1r - mn1);
        m0r = mn0; m1r = mn1;
        l0 *= cr0; l1 *= cr1;
        #pragma unroll
        for (int ni = 0; ni < 8; ni++) {
            o[ni][0] *= cr0; o[ni][1] *= cr0;
            o[ni][2] *= cr1; o[ni][3] *= cr1;
        }

        // P packed directly into A-frags (C-layout == A-layout)
        uint32_t ph0[8], ph1[8];
        #pragma unroll
        for (int ni = 0; ni < 8; ni++) {
            float p00 = __expf(s[ni][0] - mn0);
            float p01 = __expf(s[ni][1] - mn0);
            float p10 = __expf(s[ni][2] - mn1);
            float p11 = __expf(s[ni][3] - mn1);
            l0 += p00 + p01;
            l1 += p10 + p11;
            ph0[ni] = f2h2(p00, p01);
            ph1[ni] = f2h2(p10, p11);
        }

        const uint32_t vs_lanerow = vs_sb + (uint32_t)b*(64*144) + (uint32_t)(lane & 15)*144;
        #pragma unroll
        for (int ka = 0; ka < 4; ka++) {
            uint32_t a[4] = { ph0[2*ka], ph1[2*ka], ph0[2*ka+1], ph1[2*ka+1] };
            const uint32_t rowaddr = vs_lanerow + (uint32_t)(16*ka)*144;
            #pragma unroll
            for (int ni = 0; ni < 8; ni++) {
                uint32_t bf[2];
                asm volatile(
                    "ldmatrix.sync.aligned.m8n8.x2.trans.shared.b16 {%0,%1}, [%2];"
                    : "=r"(bf[0]), "=r"(bf[1]) : "r"(rowaddr + (uint32_t)(ni*16)));
                mma_f16(o[ni], a, bf);
            }
        }
    }

    // ---- finalize: write ctx as half ----
    l0 += __shfl_xor_sync(0xffffffffu, l0, 1);
    l0 += __shfl_xor_sync(0xffffffffu, l0, 2);
    l1 += __shfl_xor_sync(0xffffffffu, l1, 1);
    l1 += __shfl_xor_sync(0xffffffffu, l1, 2);
    float inv0 = 1.f / l0, inv1 = 1.f / l1;

    __half* op = g_ctxh + (size_t)qrow0*DM + h*HD;
    #pragma unroll
    for (int ni = 0; ni < 8; ni++) {
        int col = ni*8 + (tig << 1);
        *(uint32_t*)(op + col)                = f2h2(o[ni][0]*inv0, o[ni][1]*inv0);
        *(uint32_t*)(op + (size_t)8*DM + col) = f2h2(o[ni][2]*inv1, o[ni][3]*inv1);
    }
}

// ---------------------------------------------------------------------------
// Launch
// ---------------------------------------------------------------------------
extern "C" void kernel_launch(void* const* d_in, const int* in_sizes, int n_in,
                              void* d_out, int out_size)
{
    const float* x  = (const float*)d_in[0];
    const float* Wq = (const float*)d_in[1];
    const float* bq = (const float*)d_in[2];
    const float* Wk = (const float*)d_in[3];
    const float* bk = (const float*)d_in[4];
    const float* Wv = (const float*)d_in[5];
    const float* bv = (const float*)d_in[6];
    const float* Wo = (const float*)d_in[7];
    const float* bo = (const float*)d_in[8];
    float* out = (float*)d_out;

    __half *p_xh, *p_qh, *p_kh, *p_vh, *p_ctxh, *p_w4, *p_lmh, *p_lmk, *p_lmv;
    cudaGetSymbolAddress((void**)&p_xh,   g_xh);
    cudaGetSymbolAddress((void**)&p_qh,   g_qh);
    cudaGetSymbolAddress((void**)&p_kh,   g_kh);
    cudaGetSymbolAddress((void**)&p_vh,   g_vh);
    cudaGetSymbolAddress((void**)&p_ctxh, g_ctxh);
    cudaGetSymbolAddress((void**)&p_w4,   g_w4);
    cudaGetSymbolAddress((void**)&p_lmh,  g_lmh);
    cudaGetSymbolAddress((void**)&p_lmk,  g_lmk);
    cudaGetSymbolAddress((void**)&p_lmv,  g_lmv);

    cudaFuncSetAttribute(gemm_h, cudaFuncAttributeMaxDynamicSharedMemorySize, GEMM_SMEM);
    cudaFuncSetAttribute(attn_kernel, cudaFuncAttributeMaxDynamicSharedMemorySize, ATTN_SMEM);

    cvt_f2h<<<(QROWS*DM/4)/256, 256>>>(x, p_xh);
    cvt_w4<<<dim3((DM*DM/4)/256, 4), 256>>>(Wq, Wk, Wv, Wo);
    landmark_kernel<<<BATCH*NLM, DM>>>(x);

    // Q, K, V projections of x tokens, fused (shared A tiles via L2)
    GArgs aq = { p_xh, p_w4 + 0*(size_t)DM*DM, bq, p_qh, nullptr, QROWS };
    GArgs ak = { p_xh, p_w4 + 1*(size_t)DM*DM, bk, p_kh, nullptr, QROWS };
    GArgs av = { p_xh, p_w4 + 2*(size_t)DM*DM, bv, p_vh, nullptr, QROWS };
    gemm_h<<<dim3(6, QROWS/64, 3), 128, GEMM_SMEM>>>(aq, ak, av);

    // landmark K/V projections (64 live rows -> 1 m-tile of 64)
    GArgs lk = { p_lmh, p_w4 + 1*(size_t)DM*DM, bk, p_lmk, nullptr, 128 };
    GArgs lv = { p_lmh, p_w4 + 2*(size_t)DM*DM, bv, p_lmv, nullptr, 128 };
    gemm_h<<<dim3(6, 2, 2), 128, GEMM_SMEM>>>(lk, lv, lv);

    attn_kernel<<<dim3(4, NH, BATCH*NCH), 256, ATTN_SMEM>>>();

    GArgs ao = { p_ctxh, p_w4 + 3*(size_t)DM*DM, bo, nullptr, out, QROWS };
    gemm_h<<<dim3(6, QROWS/64, 1), 128, GEMM_SMEM>>>(ao, ao, ao);
}